// round 2
// baseline (speedup 1.0000x reference)
#include <cuda_runtime.h>
#include <math.h>

#define NN 2048
#define MM 128
#define INF 256
#define HH 128
#define NCHUNK 16
#define GM 4
#define NTILE 128
#define ROWS2 8

// ---------------- scratch (no allocations allowed) ----------------
__device__ float g_S[MM][NN][12];            // [x2, S1x,S1y,S1z, S2_0..4, pad] with 1/sqrt(2l+1) folded
__device__ float g_hdp[3][NN][HH];           // (silu(h@Wpre)@Wdown[l]) * gw[n] * c[w]
__device__ float g_coarse[NCHUNK][MM][9][HH];// chunked partial coarse accumulators (deterministic)
__device__ float g_CU[MM][9][HH];            // coarse @ Wup

#define MIN_STDD 0.3023568   // 0.32*1.88973/2
#define MAX_STDD 2.1920868   // 2.32*1.88973/2

// ---------------- K1: spherical harmonics + x2 ----------------
__global__ void k_sh(const float* __restrict__ gc, const float* __restrict__ cc) {
    int m = blockIdx.x;
    float cx = cc[3*m], cy = cc[3*m+1], cz = cc[3*m+2];
    const float is3  = 0.5773502691896258f;   // 1/sqrt(3)
    const float is5  = 0.4472135954999579f;   // 1/sqrt(5)
    const float s3i5 = 0.7745966692414834f;   // sqrt(3/5)
    for (int n = threadIdx.x; n < NN; n += blockDim.x) {
        float dx = gc[3*n]   - cx;
        float dy = gc[3*n+1] - cy;
        float dz = gc[3*n+2] - cz;
        float x2 = dx*dx + dy*dy + dz*dz + 3e-20f;
        float inv = rsqrtf(x2);
        float x = dx*inv, y = dy*inv, z = dz*inv;
        float4 a = make_float4(x2, x*is3, y*is3, z*is3);
        float4 b = make_float4(s3i5*x*z, s3i5*x*y,
                               (y*y - 0.5f*(x*x + z*z))*is5, s3i5*y*z);
        float4 c4 = make_float4(0.5f*s3i5*(z*z - x*x), 0.f, 0.f, 0.f);
        float* p = &g_S[m][n][0];
        *(float4*)(p)     = a;
        *(float4*)(p + 4) = b;
        *(float4*)(p + 8) = c4;
    }
}

// ---------------- K2: pre-MLP + down projections -> g_hdp ----------------
__global__ void k_pre(const float* __restrict__ h, const float* __restrict__ Wpre,
                      const float* __restrict__ bpre, const float* __restrict__ Wdown,
                      const float* __restrict__ gw) {
    __shared__ float hsm[ROWS2][INF];
    __shared__ float hss[ROWS2][HH];
    int n0 = blockIdx.x * ROWS2;
    int w  = threadIdx.x;

    // cooperative load of 8 input rows
    for (int i = threadIdx.x; i < ROWS2*INF/4; i += blockDim.x)
        ((float4*)&hsm[0][0])[i] = ((const float4*)(h + (long)n0*INF))[i];
    __syncthreads();

    float acc[ROWS2];
    float bp = bpre[w];
    #pragma unroll
    for (int r = 0; r < ROWS2; r++) acc[r] = bp;
    #pragma unroll 4
    for (int u = 0; u < INF; u++) {
        float wv = Wpre[u*HH + w];
        #pragma unroll
        for (int r = 0; r < ROWS2; r++) acc[r] += hsm[r][u] * wv;
    }
    #pragma unroll
    for (int r = 0; r < ROWS2; r++) {
        float v = acc[r];
        hss[r][w] = v / (1.0f + __expf(-v));   // silu
    }
    __syncthreads();

    // radial prefactor c(w) = (2/3) * iv^2.5 / pi^1.5 , iv = 1/(2 s^2)
    double s  = MIN_STDD + (MAX_STDD - MIN_STDD) * (double)w / 127.0;
    double iv = 1.0 / (2.0 * s * s);
    float  cw = (float)((2.0/3.0) * pow(iv, 2.5) / pow(3.14159265358979323846, 1.5));

    float gwr[ROWS2];
    #pragma unroll
    for (int r = 0; r < ROWS2; r++) gwr[r] = gw[n0 + r] * cw;

    for (int l = 0; l < 3; l++) {
        const float* Wd = Wdown + l*HH*HH;
        float a2[ROWS2];
        #pragma unroll
        for (int r = 0; r < ROWS2; r++) a2[r] = 0.f;
        #pragma unroll 4
        for (int u = 0; u < HH; u++) {
            float wv = Wd[u*HH + w];
            #pragma unroll
            for (int r = 0; r < ROWS2; r++) a2[r] += hss[r][u] * wv;
        }
        #pragma unroll
        for (int r = 0; r < ROWS2; r++)
            g_hdp[l][n0 + r][w] = a2[r] * gwr[r];
    }
}

// ---------------- K3: main down accumulation ----------------
__global__ void k_down() {
    __shared__ float Ssm[GM][NTILE][12];
    int t  = threadIdx.x;       // hidden channel w
    int m0 = blockIdx.x * GM;
    int nb = blockIdx.y * NTILE;

    // per-thread radial exponent constant: -log2(e) * iv(w)
    double s = MIN_STDD + (MAX_STDD - MIN_STDD) * (double)t / 127.0;
    float nivl2 = (float)(-1.4426950408889634 / (2.0 * s * s));

    float acc[GM][9];
    #pragma unroll
    for (int mi = 0; mi < GM; mi++)
        #pragma unroll
        for (int k = 0; k < 9; k++) acc[mi][k] = 0.f;

    // cooperative stage of S tile (4 m's x 128 n x 12 floats)
    for (int i = t; i < GM*NTILE*3; i += blockDim.x) {
        int mi = i / (NTILE*3);
        int rem = i % (NTILE*3);
        int nn = rem / 3, j = rem % 3;
        ((float4*)&Ssm[mi][nn][0])[j] = *(const float4*)&g_S[m0 + mi][nb + nn][4*j];
    }
    __syncthreads();

    #pragma unroll 2
    for (int i = 0; i < NTILE; i++) {
        int n = nb + i;
        float h0 = g_hdp[0][n][t];
        float h1 = g_hdp[1][n][t];
        float h2 = g_hdp[2][n][t];
        #pragma unroll
        for (int mi = 0; mi < GM; mi++) {
            float4 s0 = *(float4*)&Ssm[mi][i][0];
            float4 s1 = *(float4*)&Ssm[mi][i][4];
            float s2x = Ssm[mi][i][8];
            float x2 = s0.x;
            float e;
            asm("ex2.approx.f32 %0, %1;" : "=f"(e) : "f"(x2 * nivl2));
            float r = e * x2;                 // rad core (c(w), gw folded in hdp)
            float t0 = h0 * r, t1 = h1 * r, t2 = h2 * r;
            acc[mi][0] += t0;
            acc[mi][1] += t1 * s0.y;
            acc[mi][2] += t1 * s0.z;
            acc[mi][3] += t1 * s0.w;
            acc[mi][4] += t2 * s1.x;
            acc[mi][5] += t2 * s1.y;
            acc[mi][6] += t2 * s1.z;
            acc[mi][7] += t2 * s1.w;
            acc[mi][8] += t2 * s2x;
        }
    }

    #pragma unroll
    for (int mi = 0; mi < GM; mi++)
        #pragma unroll
        for (int k = 0; k < 9; k++)
            g_coarse[blockIdx.y][m0 + mi][k][t] = acc[mi][k];
}

// ---------------- K4: chunk reduce + CU = coarse @ Wup ----------------
__global__ void k_cu(const float* __restrict__ Wup) {
    int m = blockIdx.x / 9, k = blockIdx.x % 9;
    int l = (k == 0) ? 0 : (k < 4 ? 1 : 2);
    __shared__ float csm[HH];
    int t = threadIdx.x;
    float sum = 0.f;
    #pragma unroll
    for (int ch = 0; ch < NCHUNK; ch++) sum += g_coarse[ch][m][k][t];
    csm[t] = sum;
    __syncthreads();
    const float* Wl = Wup + l*HH*HH;
    float a = 0.f;
    #pragma unroll 4
    for (int u = 0; u < HH; u++) a += csm[u] * Wl[u*HH + t];
    g_CU[m][k][t] = a;
}

// ---------------- K5: up contraction + post-MLP + silu -> d_out ----------------
__global__ void k_up(const float* __restrict__ Wpost, const float* __restrict__ bpost,
                     float* __restrict__ out) {
    __shared__ float CUsm[9][HH];
    __shared__ float Ssm[16][12];
    __shared__ float osm[16][HH];
    int t = threadIdx.x;          // 512 threads
    int w = t & 127;
    int q = t >> 7;               // 0..3, handles rows q*4 .. q*4+3
    int n0 = blockIdx.x * 16;

    float acc[4] = {0.f, 0.f, 0.f, 0.f};

    for (int m = 0; m < MM; m++) {
        __syncthreads();   // protect smem from previous iteration readers
        if (t < 288)
            ((float4*)&CUsm[0][0])[t] = ((const float4*)&g_CU[m][0][0])[t];
        else if (t < 288 + 48)
            ((float4*)&Ssm[0][0])[t - 288] = ((const float4*)&g_S[m][n0][0])[t - 288];
        __syncthreads();

        float cu[9];
        #pragma unroll
        for (int k = 0; k < 9; k++) cu[k] = CUsm[k][w];
        #pragma unroll
        for (int r = 0; r < 4; r++) {
            int rr = q*4 + r;
            float4 s0 = *(float4*)&Ssm[rr][0];
            float4 s1 = *(float4*)&Ssm[rr][4];
            float s2x = Ssm[rr][8];
            float v = cu[0];
            v += cu[1]*s0.y; v += cu[2]*s0.z; v += cu[3]*s0.w;
            v += cu[4]*s1.x; v += cu[5]*s1.y; v += cu[6]*s1.z; v += cu[7]*s1.w;
            v += cu[8]*s2x;
            acc[r] += v;
        }
    }
    __syncthreads();
    #pragma unroll
    for (int r = 0; r < 4; r++) osm[q*4 + r][w] = acc[r];
    __syncthreads();

    // post GEMM + silu
    float fo[4];
    float bp = bpost[w];
    #pragma unroll
    for (int r = 0; r < 4; r++) fo[r] = bp;
    #pragma unroll 4
    for (int u = 0; u < HH; u++) {
        float wv = Wpost[u*HH + w];
        #pragma unroll
        for (int r = 0; r < 4; r++) fo[r] += osm[q*4 + r][u] * wv;
    }
    #pragma unroll
    for (int r = 0; r < 4; r++) {
        float v = fo[r];
        out[(long)(n0 + q*4 + r)*HH + w] = v / (1.0f + __expf(-v));
    }
}

// ---------------- launch ----------------
extern "C" void kernel_launch(void* const* d_in, const int* in_sizes, int n_in,
                              void* d_out, int out_size) {
    const float* h     = (const float*)d_in[0];
    const float* gc    = (const float*)d_in[1];
    const float* cc    = (const float*)d_in[2];
    const float* gw    = (const float*)d_in[3];
    const float* Wpre  = (const float*)d_in[4];
    const float* bpre  = (const float*)d_in[5];
    const float* Wdown = (const float*)d_in[6];
    const float* Wup   = (const float*)d_in[7];
    const float* Wpost = (const float*)d_in[8];
    const float* bpost = (const float*)d_in[9];
    float* out = (float*)d_out;

    k_sh  <<<MM, 256>>>(gc, cc);
    k_pre <<<NN/ROWS2, HH>>>(h, Wpre, bpre, Wdown, gw);
    k_down<<<dim3(MM/GM, NCHUNK), HH>>>();
    k_cu  <<<MM*9, HH>>>(Wup);
    k_up  <<<NN/16, 512>>>(Wpost, bpost, out);
}

// round 4
// speedup vs baseline: 1.2282x; 1.2282x over previous
#include <cuda_runtime.h>
#include <math.h>

typedef unsigned long long ull;

#define NN 2048
#define MM 128
#define INF 256
#define HH 128
#define NP (NN/2)
#define NCHUNK 16
#define GM 4
#define PTILE 64

#define MIN_STDD 0.3023568
#define MAX_STDD 2.1920868

// ---------------- scratch ----------------
// g_S2[m][npair][20]: f4[0]={k1a,k1b,k2a,k2b} f4[1]={k3a,k3b,k4a,k4b}
//                     f4[2]={k5a,k5b,k6a,k6b} f4[3]={k7a,k7b,k8a,k8b} f4[4]={x2a,x2b,0,0}
// k1..3 = dir/sqrt(3), k4..8 = l=2 SH with 1/sqrt(5) folded
__device__ float g_S2[MM][NP][20];
__device__ float g_hdp2[3][NP][HH][2];          // n-paired hidden features * gw * c(w)
__device__ float g_coarse[NCHUNK][MM][9][HH];   // chunked deterministic partials
__device__ float g_CU[MM][9][HH];

// ---------------- f32x2 helpers ----------------
__device__ __forceinline__ ull pack2(float lo, float hi){ ull r; asm("mov.b64 %0,{%1,%2};":"=l"(r):"f"(lo),"f"(hi)); return r; }
__device__ __forceinline__ float2 unpk2(ull v){ float2 f; asm("mov.b64 {%0,%1},%2;":"=f"(f.x),"=f"(f.y):"l"(v)); return f; }
__device__ __forceinline__ ull fma2(ull a, ull b, ull c){ ull d; asm("fma.rn.f32x2 %0,%1,%2,%3;":"=l"(d):"l"(a),"l"(b),"l"(c)); return d; }
__device__ __forceinline__ ull mul2(ull a, ull b){ ull d; asm("mul.rn.f32x2 %0,%1,%2;":"=l"(d):"l"(a),"l"(b)); return d; }
__device__ __forceinline__ ull add2(ull a, ull b){ ull d; asm("add.rn.f32x2 %0,%1,%2;":"=l"(d):"l"(a),"l"(b)); return d; }
__device__ __forceinline__ float ex2f(float x){ float e; asm("ex2.approx.f32 %0,%1;":"=f"(e):"f"(x)); return e; }

// ---------------- K1: spherical harmonics (n-paired layout) ----------------
__global__ void k_sh(const float* __restrict__ gc, const float* __restrict__ cc) {
    int m = blockIdx.x;
    float cx = cc[3*m], cy = cc[3*m+1], cz = cc[3*m+2];
    const float is3  = 0.5773502691896258f;
    const float is5  = 0.4472135954999579f;
    const float s3i5 = 0.7745966692414834f;
    for (int p = threadIdx.x; p < NP; p += blockDim.x) {
        float k[2][9]; float xx2[2];
        #pragma unroll
        for (int hh = 0; hh < 2; hh++) {
            int n = 2*p + hh;
            float dx = gc[3*n]   - cx;
            float dy = gc[3*n+1] - cy;
            float dz = gc[3*n+2] - cz;
            float x2 = dx*dx + dy*dy + dz*dz + 3e-20f;
            float inv = rsqrtf(x2);
            float x = dx*inv, y = dy*inv, z = dz*inv;
            xx2[hh] = x2;
            k[hh][1] = x*is3;  k[hh][2] = y*is3;  k[hh][3] = z*is3;
            k[hh][4] = s3i5*x*z; k[hh][5] = s3i5*x*y;
            k[hh][6] = (y*y - 0.5f*(x*x + z*z))*is5;
            k[hh][7] = s3i5*y*z; k[hh][8] = 0.5f*s3i5*(z*z - x*x);
        }
        float* q = &g_S2[m][p][0];
        *(float4*)(q+0)  = make_float4(k[0][1],k[1][1],k[0][2],k[1][2]);
        *(float4*)(q+4)  = make_float4(k[0][3],k[1][3],k[0][4],k[1][4]);
        *(float4*)(q+8)  = make_float4(k[0][5],k[1][5],k[0][6],k[1][6]);
        *(float4*)(q+12) = make_float4(k[0][7],k[1][7],k[0][8],k[1][8]);
        *(float4*)(q+16) = make_float4(xx2[0],xx2[1],0.f,0.f);
    }
}

// ---------------- K2: pre-MLP + down projections (row-paired f32x2) ----------------
__global__ void __launch_bounds__(64) k_pre(const float* __restrict__ h,
                      const float* __restrict__ Wpre, const float* __restrict__ bpre,
                      const float* __restrict__ Wdown, const float* __restrict__ gw) {
    __shared__ float hT[INF][18];   // transposed, pad 18
    __shared__ float sT[HH][18];
    int n0 = blockIdx.x * 16;
    int t  = threadIdx.x;           // 64 threads, cols w0=t, w1=t+64

    for (int idx = t; idx < 16*INF; idx += 64) {
        int r = idx >> 8, u = idx & 255;
        hT[u][r] = h[(n0 + r)*INF + u];
    }
    __syncthreads();

    int w0 = t, w1 = t + 64;
    ull acc[2][8];
    {
        float b0 = bpre[w0], b1 = bpre[w1];
        #pragma unroll
        for (int j = 0; j < 8; j++) { acc[0][j] = pack2(b0,b0); acc[1][j] = pack2(b1,b1); }
    }
    #pragma unroll 4
    for (int u = 0; u < INF; u++) {
        float wa = Wpre[u*HH + w0], wb = Wpre[u*HH + w1];
        ull w2a = pack2(wa,wa), w2b = pack2(wb,wb);
        #pragma unroll
        for (int j = 0; j < 8; j++) {
            ull hp = *(const ull*)&hT[u][2*j];
            acc[0][j] = fma2(hp, w2a, acc[0][j]);
            acc[1][j] = fma2(hp, w2b, acc[1][j]);
        }
    }
    #pragma unroll
    for (int j = 0; j < 8; j++) {
        float2 a = unpk2(acc[0][j]);
        float2 b = unpk2(acc[1][j]);
        a.x = a.x/(1.f+__expf(-a.x)); a.y = a.y/(1.f+__expf(-a.y));
        b.x = b.x/(1.f+__expf(-b.x)); b.y = b.y/(1.f+__expf(-b.y));
        *(ull*)&sT[w0][2*j] = pack2(a.x, a.y);
        *(ull*)&sT[w1][2*j] = pack2(b.x, b.y);
    }
    __syncthreads();

    // radial prefactor c(w) per column
    double s0d = MIN_STDD + (MAX_STDD-MIN_STDD)*(double)w0/127.0;
    double s1d = MIN_STDD + (MAX_STDD-MIN_STDD)*(double)w1/127.0;
    double iv0 = 1.0/(2.0*s0d*s0d), iv1 = 1.0/(2.0*s1d*s1d);
    const double pi15 = 5.568327996831708;  // pi^1.5
    float cw0 = (float)((2.0/3.0)*pow(iv0,2.5)/pi15);
    float cw1 = (float)((2.0/3.0)*pow(iv1,2.5)/pi15);

    ull gwc0[8], gwc1[8];
    #pragma unroll
    for (int j = 0; j < 8; j++) {
        float glo = gw[n0 + 2*j], ghi = gw[n0 + 2*j + 1];
        gwc0[j] = pack2(glo*cw0, ghi*cw0);
        gwc1[j] = pack2(glo*cw1, ghi*cw1);
    }

    int pbase = blockIdx.x * 8;
    for (int l = 0; l < 3; l++) {
        const float* Wd = Wdown + l*HH*HH;
        ull a2[2][8];
        #pragma unroll
        for (int j = 0; j < 8; j++) { a2[0][j] = 0ull; a2[1][j] = 0ull; }
        #pragma unroll 4
        for (int u = 0; u < HH; u++) {
            float wa = Wd[u*HH + w0], wb = Wd[u*HH + w1];
            ull w2a = pack2(wa,wa), w2b = pack2(wb,wb);
            #pragma unroll
            for (int j = 0; j < 8; j++) {
                ull sp = *(const ull*)&sT[u][2*j];
                a2[0][j] = fma2(sp, w2a, a2[0][j]);
                a2[1][j] = fma2(sp, w2b, a2[1][j]);
            }
        }
        #pragma unroll
        for (int j = 0; j < 8; j++) {
            *(ull*)&g_hdp2[l][pbase + j][w0][0] = mul2(a2[0][j], gwc0[j]);
            *(ull*)&g_hdp2[l][pbase + j][w1][0] = mul2(a2[1][j], gwc1[j]);
        }
    }
}

// ---------------- K3: main down accumulation (n-paired f32x2) ----------------
__global__ void __launch_bounds__(128) k_down() {
    __shared__ float Ssm[GM][PTILE][20];
    int t  = threadIdx.x;
    int m0 = blockIdx.x * GM;
    int p0 = blockIdx.y * PTILE;

    double sd = MIN_STDD + (MAX_STDD-MIN_STDD)*(double)t/127.0;
    float niv = (float)(-1.4426950408889634/(2.0*sd*sd));
    ull niv2 = pack2(niv, niv);

    for (int i = t; i < GM*PTILE*5; i += 128) {
        int mi = i/(PTILE*5); int rem = i%(PTILE*5); int p = rem/5; int j = rem%5;
        *(float4*)&Ssm[mi][p][4*j] = *(const float4*)&g_S2[m0+mi][p0+p][4*j];
    }
    ull acc[GM][9];
    #pragma unroll
    for (int mi = 0; mi < GM; mi++)
        #pragma unroll
        for (int k = 0; k < 9; k++) acc[mi][k] = 0ull;
    __syncthreads();

    ull h0 = *(const ull*)&g_hdp2[0][p0][t][0];
    ull h1 = *(const ull*)&g_hdp2[1][p0][t][0];
    ull h2 = *(const ull*)&g_hdp2[2][p0][t][0];

    #pragma unroll 1
    for (int p = 0; p < PTILE; p++) {
        ull c0 = h0, c1 = h1, c2 = h2;
        if (p + 1 < PTILE) {
            h0 = *(const ull*)&g_hdp2[0][p0+p+1][t][0];
            h1 = *(const ull*)&g_hdp2[1][p0+p+1][t][0];
            h2 = *(const ull*)&g_hdp2[2][p0+p+1][t][0];
        }
        #pragma unroll
        for (int mi = 0; mi < GM; mi++) {
            const float* sp = &Ssm[mi][p][0];
            ulonglong2 q01 = *(const ulonglong2*)(sp);
            ulonglong2 q23 = *(const ulonglong2*)(sp + 4);
            ulonglong2 q45 = *(const ulonglong2*)(sp + 8);
            ulonglong2 q67 = *(const ulonglong2*)(sp + 12);
            ull x2p = *(const ull*)(sp + 16);
            ull qq  = mul2(x2p, niv2);
            float2 ef = unpk2(qq);
            ull ep  = pack2(ex2f(ef.x), ex2f(ef.y));
            ull rp  = mul2(ep, x2p);
            ull t0 = mul2(c0, rp), t1 = mul2(c1, rp), t2 = mul2(c2, rp);
            acc[mi][0] = add2(acc[mi][0], t0);
            acc[mi][1] = fma2(t1, q01.x, acc[mi][1]);
            acc[mi][2] = fma2(t1, q01.y, acc[mi][2]);
            acc[mi][3] = fma2(t1, q23.x, acc[mi][3]);
            acc[mi][4] = fma2(t2, q23.y, acc[mi][4]);
            acc[mi][5] = fma2(t2, q45.x, acc[mi][5]);
            acc[mi][6] = fma2(t2, q45.y, acc[mi][6]);
            acc[mi][7] = fma2(t2, q67.x, acc[mi][7]);
            acc[mi][8] = fma2(t2, q67.y, acc[mi][8]);
        }
    }
    #pragma unroll
    for (int mi = 0; mi < GM; mi++)
        #pragma unroll
        for (int k = 0; k < 9; k++) {
            float2 f = unpk2(acc[mi][k]);
            g_coarse[blockIdx.y][m0+mi][k][t] = f.x + f.y;
        }
}

// ---------------- K4: chunk reduce + CU = coarse @ Wup (m-paired f32x2) ----------------
__global__ void __launch_bounds__(128) k_cu(const float* __restrict__ Wup) {
    __shared__ ull a2u[4][HH];
    int bx = blockIdx.x;
    int kk = bx >> 4;            // 0..8
    int mt = bx & 15;            // 0..15
    int m0 = mt * 8;
    int l  = (kk == 0) ? 0 : (kk < 4 ? 1 : 2);
    int t  = threadIdx.x;

    #pragma unroll
    for (int j = 0; j < 4; j++) {
        float lo = 0.f, hi = 0.f;
        #pragma unroll
        for (int ch = 0; ch < NCHUNK; ch++) {
            lo += g_coarse[ch][m0+2*j  ][kk][t];
            hi += g_coarse[ch][m0+2*j+1][kk][t];
        }
        a2u[j][t] = pack2(lo, hi);
    }
    __syncthreads();

    const float* Wl = Wup + l*HH*HH;
    ull acc[4] = {0ull, 0ull, 0ull, 0ull};
    #pragma unroll 8
    for (int u = 0; u < HH; u++) {
        float wv = Wl[u*HH + t];
        ull wv2 = pack2(wv, wv);
        #pragma unroll
        for (int j = 0; j < 4; j++) acc[j] = fma2(a2u[j][u], wv2, acc[j]);
    }
    #pragma unroll
    for (int j = 0; j < 4; j++) {
        float2 f = unpk2(acc[j]);
        g_CU[m0+2*j  ][kk][t] = f.x;
        g_CU[m0+2*j+1][kk][t] = f.y;
    }
}

// ---------------- K5: up contraction + post-MLP (double-buffered, n-paired) ----------------
__global__ void __launch_bounds__(512) k_up(const float* __restrict__ Wpost,
                                            const float* __restrict__ bpost,
                                            float* __restrict__ out) {
    __shared__ float CUsm[2][1152];
    __shared__ float Ssm[2][160];
    __shared__ ull  osm[8][HH];
    int t = threadIdx.x;
    int w = t & 127, q = t >> 7;
    int p0 = blockIdx.x * 8;      // 8 n-pairs = 16 rows

    bool doCU = (t < 288);
    bool doS  = (t >= 288 && t < 328);
    int  si   = t - 288;

    float4 rCU, rS;
    if (doCU) rCU = ((const float4*)&g_CU[0][0][0])[t];
    if (doS)  rS  = *(const float4*)(&g_S2[0][p0][0] + 4*si);
    if (doCU) *(((float4*)&CUsm[0][0]) + t) = rCU;
    if (doS)  *(((float4*)&Ssm[0][0]) + si) = rS;
    __syncthreads();

    ull acc0 = 0ull, acc1 = 0ull;
    #pragma unroll 1
    for (int m = 0; m < MM; m++) {
        int buf = m & 1;
        if (m + 1 < MM) {
            if (doCU) rCU = ((const float4*)&g_CU[m+1][0][0])[t];
            if (doS)  rS  = *(const float4*)(&g_S2[m+1][p0][0] + 4*si);
        }
        ull cu[9];
        #pragma unroll
        for (int k = 0; k < 9; k++) { float c = CUsm[buf][k*HH + w]; cu[k] = pack2(c, c); }
        #pragma unroll
        for (int i = 0; i < 2; i++) {
            int rp = q*2 + i;
            const float* sp = &Ssm[buf][rp*20];
            ulonglong2 q01 = *(const ulonglong2*)(sp);
            ulonglong2 q23 = *(const ulonglong2*)(sp + 4);
            ulonglong2 q45 = *(const ulonglong2*)(sp + 8);
            ulonglong2 q67 = *(const ulonglong2*)(sp + 12);
            ull a = i ? acc1 : acc0;
            a = add2(a, cu[0]);
            a = fma2(cu[1], q01.x, a);
            a = fma2(cu[2], q01.y, a);
            a = fma2(cu[3], q23.x, a);
            a = fma2(cu[4], q23.y, a);
            a = fma2(cu[5], q45.x, a);
            a = fma2(cu[6], q45.y, a);
            a = fma2(cu[7], q67.x, a);
            a = fma2(cu[8], q67.y, a);
            if (i) acc1 = a; else acc0 = a;
        }
        if (m + 1 < MM) {
            int nb = buf ^ 1;
            if (doCU) *(((float4*)&CUsm[nb][0]) + t) = rCU;
            if (doS)  *(((float4*)&Ssm[nb][0]) + si) = rS;
        }
        __syncthreads();
    }

    osm[q*2 + 0][w] = acc0;
    osm[q*2 + 1][w] = acc1;
    __syncthreads();

    float bp = bpost[w];
    ull fo0 = pack2(bp, bp), fo1 = pack2(bp, bp);
    #pragma unroll 8
    for (int u = 0; u < HH; u++) {
        float wv = Wpost[u*HH + w];
        ull wv2 = pack2(wv, wv);
        fo0 = fma2(osm[q*2 + 0][u], wv2, fo0);
        fo1 = fma2(osm[q*2 + 1][u], wv2, fo1);
    }
    float2 f0 = unpk2(fo0), f1 = unpk2(fo1);
    int r0 = 2*p0 + 4*q;
    out[(long)(r0+0)*HH + w] = f0.x/(1.f+__expf(-f0.x));
    out[(long)(r0+1)*HH + w] = f0.y/(1.f+__expf(-f0.y));
    out[(long)(r0+2)*HH + w] = f1.x/(1.f+__expf(-f1.x));
    out[(long)(r0+3)*HH + w] = f1.y/(1.f+__expf(-f1.y));
}

// ---------------- launch ----------------
extern "C" void kernel_launch(void* const* d_in, const int* in_sizes, int n_in,
                              void* d_out, int out_size) {
    const float* h     = (const float*)d_in[0];
    const float* gc    = (const float*)d_in[1];
    const float* cc    = (const float*)d_in[2];
    const float* gw    = (const float*)d_in[3];
    const float* Wpre  = (const float*)d_in[4];
    const float* bpre  = (const float*)d_in[5];
    const float* Wdown = (const float*)d_in[6];
    const float* Wup   = (const float*)d_in[7];
    const float* Wpost = (const float*)d_in[8];
    const float* bpost = (const float*)d_in[9];
    float* out = (float*)d_out;

    k_sh  <<<MM, 256>>>(gc, cc);
    k_pre <<<NN/16, 64>>>(h, Wpre, bpre, Wdown, gw);
    k_down<<<dim3(MM/GM, NCHUNK), 128>>>();
    k_cu  <<<144, 128>>>(Wup);
    k_up  <<<NP/8, 512>>>(Wpost, bpost, out);
}